// round 1
// baseline (speedup 1.0000x reference)
#include <cuda_runtime.h>
#include <math_constants.h>

typedef long long ll;

// Problem constants
constexpr int Lc   = 2;
constexpr int Bc   = 4;
constexpr int Tc   = 2048;
constexpr int Fc   = 1024;
constexpr int Cc   = 200;
constexpr int Hc   = 8;
constexpr int DFFc = 128;
constexpr int Sc   = Tc + Cc;   // 2248
constexpr int BSc  = Bc * Sc;   // 8992
constexpr int DHc  = Fc / Hc;   // 128

// ---------------------------------------------------------------------------
// Scratch (device globals; no allocations allowed)
// ---------------------------------------------------------------------------
__device__ float d_src [(size_t)BSc * Fc];
__device__ float d_qb  [(size_t)BSc * Fc];
__device__ float d_kb  [(size_t)BSc * Fc];
__device__ float d_vb  [(size_t)BSc * Fc];
__device__ float d_att [(size_t)BSc * Fc];
__device__ float d_tmp [(size_t)BSc * Fc];
__device__ float d_ffh [(size_t)BSc * DFFc];
__device__ float d_probs[(size_t)Bc * Hc * Sc * Sc];       // ~647 MB
__device__ float d_wfq [Fc * Fc];
__device__ float d_wfk [Fc * Fc];
__device__ float d_bfq [Fc];
__device__ float d_bfk [Fc];
__device__ float d_icol[(size_t)Bc * Tc * 3 * Fc];
__device__ float d_ct  [(size_t)Bc * Tc * Fc];

// ---------------------------------------------------------------------------
// Block reductions
// ---------------------------------------------------------------------------
__device__ __forceinline__ float blkReduceSum(float v) {
    __shared__ float sh[32];
    int lane = threadIdx.x & 31, w = threadIdx.x >> 5;
    #pragma unroll
    for (int o = 16; o; o >>= 1) v += __shfl_xor_sync(0xffffffffu, v, o);
    if (lane == 0) sh[w] = v;
    __syncthreads();
    int nw = blockDim.x >> 5;
    float r = (lane < nw) ? sh[lane] : 0.f;
    #pragma unroll
    for (int o = 16; o; o >>= 1) r += __shfl_xor_sync(0xffffffffu, r, o);
    __syncthreads();
    return r;
}

__device__ __forceinline__ float blkReduceMax(float v) {
    __shared__ float sh[32];
    int lane = threadIdx.x & 31, w = threadIdx.x >> 5;
    #pragma unroll
    for (int o = 16; o; o >>= 1) v = fmaxf(v, __shfl_xor_sync(0xffffffffu, v, o));
    if (lane == 0) sh[w] = v;
    __syncthreads();
    int nw = blockDim.x >> 5;
    float r = (lane < nw) ? sh[lane] : -CUDART_INF_F;
    #pragma unroll
    for (int o = 16; o; o >>= 1) r = fmaxf(r, __shfl_xor_sync(0xffffffffu, r, o));
    __syncthreads();
    return r;
}

// ---------------------------------------------------------------------------
// Generic tiled SGEMM (fp32).
//   C[m,n] = alpha * sum_k A[m,k] * B(n,k)  (+ bias[n]) (+ relu)
//   B(n,k) = BT ? Bm[n*ldb + k] : Bm[k*ldb + n]
// Batched via blockIdx.z with (outer, inner) stride decomposition
// (z = zb*batchH + zh). Assumes K % 4 == 0 and N % 4 == 0 (true for all uses).
// Tile 64x64x16, 256 threads, 4x4 per-thread microtile, float4 paths.
// ---------------------------------------------------------------------------
template<bool BT, bool HASBIAS, bool DORELU>
__global__ void __launch_bounds__(256)
sgemm_kernel(int M, int N, int K,
             const float* __restrict__ A, int lda,
             const float* __restrict__ Bm, int ldb,
             float* __restrict__ Cm, int ldc,
             const float* __restrict__ bias, float alpha,
             int batchH,
             ll sAb, ll sAh, ll sBb, ll sBh, ll sCb, ll sCh)
{
    {
        int z = blockIdx.z;
        int zb = z / batchH;
        int zh = z - zb * batchH;
        A  += zb * sAb + zh * sAh;
        Bm += zb * sBb + zh * sBh;
        Cm += zb * sCb + zh * sCh;
    }

    __shared__ float As[16][64];
    __shared__ float Bs[16][64];

    const int t  = threadIdx.x;
    const int tx = t & 15, ty = t >> 4;
    const int m0 = blockIdx.y * 64, n0 = blockIdx.x * 64;

    const int ai  = t >> 2;          // 0..63
    const int ak  = (t & 3) << 2;    // 0,4,8,12
    const int bkk = t >> 4;          // 0..15 (non-transposed B)
    const int bj  = (t & 15) << 2;   // 0..60

    float acc[4][4] = {};

    for (int k0 = 0; k0 < K; k0 += 16) {
        // --- load A tile (As[k][m]) ---
        {
            float4 v = make_float4(0.f, 0.f, 0.f, 0.f);
            int m = m0 + ai, k = k0 + ak;
            if (m < M && k < K) v = *(const float4*)(A + (ll)m * lda + k);
            As[ak + 0][ai] = v.x; As[ak + 1][ai] = v.y;
            As[ak + 2][ai] = v.z; As[ak + 3][ai] = v.w;
        }
        // --- load B tile (Bs[k][n]) ---
        if (BT) {
            float4 v = make_float4(0.f, 0.f, 0.f, 0.f);
            int n = n0 + ai, k = k0 + ak;
            if (n < N && k < K) v = *(const float4*)(Bm + (ll)n * ldb + k);
            Bs[ak + 0][ai] = v.x; Bs[ak + 1][ai] = v.y;
            Bs[ak + 2][ai] = v.z; Bs[ak + 3][ai] = v.w;
        } else {
            float4 v = make_float4(0.f, 0.f, 0.f, 0.f);
            int k = k0 + bkk, n = n0 + bj;
            if (k < K && n < N) v = *(const float4*)(Bm + (ll)k * ldb + n);
            *(float4*)&Bs[bkk][bj] = v;
        }
        __syncthreads();

        #pragma unroll
        for (int kk = 0; kk < 16; kk++) {
            float4 a = *(const float4*)&As[kk][ty << 2];
            float4 b = *(const float4*)&Bs[kk][tx << 2];
            acc[0][0] += a.x * b.x; acc[0][1] += a.x * b.y;
            acc[0][2] += a.x * b.z; acc[0][3] += a.x * b.w;
            acc[1][0] += a.y * b.x; acc[1][1] += a.y * b.y;
            acc[1][2] += a.y * b.z; acc[1][3] += a.y * b.w;
            acc[2][0] += a.z * b.x; acc[2][1] += a.z * b.y;
            acc[2][2] += a.z * b.z; acc[2][3] += a.z * b.w;
            acc[3][0] += a.w * b.x; acc[3][1] += a.w * b.y;
            acc[3][2] += a.w * b.z; acc[3][3] += a.w * b.w;
        }
        __syncthreads();
    }

    // --- epilogue ---
    const int n = n0 + (tx << 2);
    if (n < N) {
        float bx = 0.f, by = 0.f, bz = 0.f, bw = 0.f;
        if (HASBIAS) { bx = bias[n]; by = bias[n + 1]; bz = bias[n + 2]; bw = bias[n + 3]; }
        #pragma unroll
        for (int i = 0; i < 4; i++) {
            int m = m0 + (ty << 2) + i;
            if (m >= M) break;
            float4 o;
            o.x = acc[i][0] * alpha + bx;
            o.y = acc[i][1] * alpha + by;
            o.z = acc[i][2] * alpha + bz;
            o.w = acc[i][3] * alpha + bw;
            if (DORELU) {
                o.x = fmaxf(o.x, 0.f); o.y = fmaxf(o.y, 0.f);
                o.z = fmaxf(o.z, 0.f); o.w = fmaxf(o.w, 0.f);
            }
            *(float4*)(Cm + (ll)m * ldc + n) = o;
        }
    }
}

// ---------------------------------------------------------------------------
// Small kernels
// ---------------------------------------------------------------------------
__global__ void copy_x_kernel(const float* __restrict__ x, float* __restrict__ src) {
    int idx = blockIdx.x * 256 + threadIdx.x;
    if (idx >= Bc * Tc * Fc) return;
    int b = idx / (Tc * Fc);
    int r = idx - b * (Tc * Fc);
    src[(size_t)b * Sc * Fc + r] = x[idx];
}

// torch: prototypes.view(1, F, -1): proto_col[f, c] = flat[f*C + c]
// src[b, T+c, f] = flat[f*C + c]
__global__ void fill_proto_kernel(const float* __restrict__ proto, float* __restrict__ src) {
    int idx = blockIdx.x * 256 + threadIdx.x;
    if (idx >= Bc * Cc * Fc) return;
    int b   = idx / (Cc * Fc);
    int rem = idx - b * (Cc * Fc);
    int c   = rem / Fc;
    int f   = rem - c * Fc;
    src[(size_t)b * Sc * Fc + (size_t)(Tc + c) * Fc + f] = proto[(size_t)f * Cc + c];
}

// fused bias: outb[n] = badd[n] + sum_t Wi[n,t] * bsmall[t]
__global__ void fuse_bias_kernel(const float* __restrict__ Wi,
                                 const float* __restrict__ bsmall,
                                 const float* __restrict__ badd,
                                 float* __restrict__ outb) {
    int n = blockIdx.x;
    float s = 0.f;
    for (int t = threadIdx.x; t < Fc; t += 256) s += Wi[(size_t)n * Fc + t] * bsmall[t];
    s = blkReduceSum(s);
    if (threadIdx.x == 0) outb[n] = s + badd[n];
}

__global__ void softmax_kernel(float* __restrict__ p) {
    size_t row = blockIdx.x;
    float* r = p + row * (size_t)Sc;
    float vals[9];
    float m = -CUDART_INF_F;
    int cnt = 0;
    for (int i = threadIdx.x; i < Sc; i += 256) {
        float v = r[i];
        vals[cnt++] = v;
        m = fmaxf(m, v);
    }
    m = blkReduceMax(m);
    float s = 0.f;
    for (int j = 0; j < cnt; j++) { vals[j] = __expf(vals[j] - m); s += vals[j]; }
    s = blkReduceSum(s);
    float inv = 1.f / s;
    cnt = 0;
    for (int i = threadIdx.x; i < Sc; i += 256) r[i] = vals[cnt++] * inv;
}

// src = LN(src + delta) row-wise, F=1024, block=256
__global__ void ln_add_kernel(float* __restrict__ src, const float* __restrict__ delta,
                              const float* __restrict__ g, const float* __restrict__ b) {
    size_t row = blockIdx.x;
    float* sp = src + row * Fc;
    const float* dp = delta + row * Fc;
    float x[4];
    float s = 0.f;
    #pragma unroll
    for (int j = 0; j < 4; j++) {
        int i = threadIdx.x + j * 256;
        x[j] = sp[i] + dp[i];
        s += x[j];
    }
    float mean = blkReduceSum(s) * (1.f / Fc);
    float s2 = 0.f;
    #pragma unroll
    for (int j = 0; j < 4; j++) { float d = x[j] - mean; s2 += d * d; }
    float var = blkReduceSum(s2) * (1.f / Fc);
    float rstd = rsqrtf(var + 1e-5f);
    #pragma unroll
    for (int j = 0; j < 4; j++) {
        int i = threadIdx.x + j * 256;
        sp[i] = (x[j] - mean) * rstd * g[i] + b[i];
    }
}

// im2col: col[b, t, fi*3+kk] = src[b, t+kk-1, fi] (0 outside [0,T))
__global__ void im2col_kernel(const float* __restrict__ src, float* __restrict__ col) {
    int idx = blockIdx.x * 256 + threadIdx.x;
    if (idx >= Bc * Tc * 3 * Fc) return;
    int c3 = idx % (3 * Fc);
    int bt = idx / (3 * Fc);
    int t = bt % Tc, b = bt / Tc;
    int fi = c3 / 3, kk = c3 - fi * 3;
    int tt = t + kk - 1;
    float v = 0.f;
    if (tt >= 0 && tt < Tc) v = src[(size_t)b * Sc * Fc + (size_t)tt * Fc + fi];
    col[idx] = v;
}

// out[b, f, t] = relu(in[b, t, f]); block (32,8), grid (T/32, F/32, B)
__global__ void transpose_relu_kernel(const float* __restrict__ in, float* __restrict__ outp) {
    __shared__ float tile[32][33];
    int b = blockIdx.z;
    int t0 = blockIdx.x * 32, f0 = blockIdx.y * 32;
    int tx = threadIdx.x, ty = threadIdx.y;
    #pragma unroll
    for (int i = 0; i < 4; i++) {
        int tt = t0 + ty + i * 8;
        tile[ty + i * 8][tx] = in[(size_t)b * Tc * Fc + (size_t)tt * Fc + f0 + tx];
    }
    __syncthreads();
    #pragma unroll
    for (int i = 0; i < 4; i++) {
        int f = f0 + ty + i * 8;
        float v = tile[tx][ty + i * 8];
        outp[(size_t)b * Fc * Tc + (size_t)f * Tc + t0 + tx] = fmaxf(v, 0.f);
    }
}

// ---------------------------------------------------------------------------
// Host dispatch
// ---------------------------------------------------------------------------
static void launch_gemm(bool bt, bool hasbias, bool dorelu,
                        int M, int N, int K,
                        const float* A, int lda, const float* B, int ldb,
                        float* C, int ldc, const float* bias, float alpha,
                        int nz = 1, int batchH = 1,
                        ll sAb = 0, ll sAh = 0, ll sBb = 0, ll sBh = 0,
                        ll sCb = 0, ll sCh = 0)
{
    dim3 grid((N + 63) / 64, (M + 63) / 64, nz);
    if (!bt && !hasbias && !dorelu)
        sgemm_kernel<false, false, false><<<grid, 256>>>(M, N, K, A, lda, B, ldb, C, ldc,
            bias, alpha, batchH, sAb, sAh, sBb, sBh, sCb, sCh);
    else if (bt && hasbias && !dorelu)
        sgemm_kernel<true, true, false><<<grid, 256>>>(M, N, K, A, lda, B, ldb, C, ldc,
            bias, alpha, batchH, sAb, sAh, sBb, sBh, sCb, sCh);
    else if (bt && !hasbias && !dorelu)
        sgemm_kernel<true, false, false><<<grid, 256>>>(M, N, K, A, lda, B, ldb, C, ldc,
            bias, alpha, batchH, sAb, sAh, sBb, sBh, sCb, sCh);
    else
        sgemm_kernel<true, true, true><<<grid, 256>>>(M, N, K, A, lda, B, ldb, C, ldc,
            bias, alpha, batchH, sAb, sAh, sBb, sBh, sCb, sCh);
}

extern "C" void kernel_launch(void* const* d_in, const int* in_sizes, int n_in,
                              void* d_out, int out_size)
{
    const float* x      = (const float*)d_in[0];
    const float* proto  = (const float*)d_in[1];
    const float* wq     = (const float*)d_in[2];
    const float* bq     = (const float*)d_in[3];
    const float* wk     = (const float*)d_in[4];
    const float* bk     = (const float*)d_in[5];
    const float* in_w   = (const float*)d_in[6];
    const float* in_b   = (const float*)d_in[7];
    const float* out_w  = (const float*)d_in[8];
    const float* out_b  = (const float*)d_in[9];
    const float* l1w    = (const float*)d_in[10];
    const float* l1b    = (const float*)d_in[11];
    const float* l2w    = (const float*)d_in[12];
    const float* l2b    = (const float*)d_in[13];
    const float* ln1g   = (const float*)d_in[14];
    const float* ln1b   = (const float*)d_in[15];
    const float* ln2g   = (const float*)d_in[16];
    const float* ln2b   = (const float*)d_in[17];
    const float* embw   = (const float*)d_in[18];
    const float* embb   = (const float*)d_in[19];
    float* out = (float*)d_out;

    float *src, *q, *k, *v, *att, *tmp, *ffh, *probs, *wfq, *wfk, *bfq, *bfk, *icol, *ct;
    cudaGetSymbolAddress((void**)&src,  d_src);
    cudaGetSymbolAddress((void**)&q,    d_qb);
    cudaGetSymbolAddress((void**)&k,    d_kb);
    cudaGetSymbolAddress((void**)&v,    d_vb);
    cudaGetSymbolAddress((void**)&att,  d_att);
    cudaGetSymbolAddress((void**)&tmp,  d_tmp);
    cudaGetSymbolAddress((void**)&ffh,  d_ffh);
    cudaGetSymbolAddress((void**)&probs, d_probs);
    cudaGetSymbolAddress((void**)&wfq,  d_wfq);
    cudaGetSymbolAddress((void**)&wfk,  d_wfk);
    cudaGetSymbolAddress((void**)&bfq,  d_bfq);
    cudaGetSymbolAddress((void**)&bfk,  d_bfk);
    cudaGetSymbolAddress((void**)&icol, d_icol);
    cudaGetSymbolAddress((void**)&ct,   d_ct);

    const float scale = 0.08838834764831845f;  // 1/sqrt(128)

    // Build src = concat(x, scrambled prototypes) in (B, S, F)
    copy_x_kernel<<<(Bc * Tc * Fc + 255) / 256, 256>>>(x, src);
    fill_proto_kernel<<<(Bc * Cc * Fc + 255) / 256, 256>>>(proto, src);

    for (int l = 0; l < Lc; l++) {
        const float* Wi   = in_w + (ll)l * 3 * Fc * Fc;   // [3F, F]
        const float* Wiq  = Wi;
        const float* Wik  = Wi + (ll)Fc * Fc;
        const float* Wiv  = Wi + (ll)2 * Fc * Fc;
        const float* bin  = in_b + (ll)l * 3 * Fc;

        // Fuse 1x1 conv into in-proj:  Wfq = Wiq @ wq[l],  Wfk = Wik @ wk[l]
        launch_gemm(false, false, false, Fc, Fc, Fc,
                    Wiq, Fc, wq + (ll)l * Fc * Fc, Fc, wfq, Fc, nullptr, 1.f);
        launch_gemm(false, false, false, Fc, Fc, Fc,
                    Wik, Fc, wk + (ll)l * Fc * Fc, Fc, wfk, Fc, nullptr, 1.f);
        fuse_bias_kernel<<<Fc, 256>>>(Wiq, bq + (ll)l * Fc, bin,          bfq);
        fuse_bias_kernel<<<Fc, 256>>>(Wik, bk + (ll)l * Fc, bin + Fc,     bfk);

        // Q, K, V : (BS, F)
        launch_gemm(true, true, false, BSc, Fc, Fc, src, Fc, wfq, Fc, q, Fc, bfq, 1.f);
        launch_gemm(true, true, false, BSc, Fc, Fc, src, Fc, wfk, Fc, k, Fc, bfk, 1.f);
        launch_gemm(true, true, false, BSc, Fc, Fc, src, Fc, Wiv, Fc, v, Fc, bin + 2 * Fc, 1.f);

        // scores = scale * Q_h K_h^T   (batched over b,h)
        launch_gemm(true, false, false, Sc, Sc, DHc,
                    q, Fc, k, Fc, probs, Sc, nullptr, scale,
                    Bc * Hc, Hc,
                    (ll)Sc * Fc, DHc, (ll)Sc * Fc, DHc,
                    (ll)Hc * Sc * Sc, (ll)Sc * Sc);
        softmax_kernel<<<Bc * Hc * Sc, 256>>>(probs);

        // att = P V   (batched over b,h)
        launch_gemm(false, false, false, Sc, DHc, Sc,
                    probs, Sc, v, Fc, att, Fc, nullptr, 1.f,
                    Bc * Hc, Hc,
                    (ll)Hc * Sc * Sc, (ll)Sc * Sc,
                    (ll)Sc * Fc, DHc, (ll)Sc * Fc, DHc);

        // out-proj + residual LN
        launch_gemm(true, true, false, BSc, Fc, Fc,
                    att, Fc, out_w + (ll)l * Fc * Fc, Fc, tmp, Fc, out_b + (ll)l * Fc, 1.f);
        ln_add_kernel<<<BSc, 256>>>(src, tmp, ln1g + (ll)l * Fc, ln1b + (ll)l * Fc);

        // FFN + residual LN
        launch_gemm(true, true, true, BSc, DFFc, Fc,
                    src, Fc, l1w + (ll)l * DFFc * Fc, Fc, ffh, DFFc, l1b + (ll)l * DFFc, 1.f);
        launch_gemm(true, true, false, BSc, Fc, DFFc,
                    ffh, DFFc, l2w + (ll)l * Fc * DFFc, DFFc, tmp, Fc, l2b + (ll)l * Fc, 1.f);
        ln_add_kernel<<<BSc, 256>>>(src, tmp, ln2g + (ll)l * Fc, ln2b + (ll)l * Fc);
    }

    // Conv1d(F->F, k=3, pad=1) over the first T tokens, as im2col GEMM
    im2col_kernel<<<(Bc * Tc * 3 * Fc + 255) / 256, 256>>>(src, icol);
    launch_gemm(true, true, false, Bc * Tc, Fc, 3 * Fc,
                icol, 3 * Fc, embw, 3 * Fc, ct, Fc, embb, 1.f);

    // (B,T,F) -> (B,F,T) with ReLU
    transpose_relu_kernel<<<dim3(Tc / 32, Fc / 32, Bc), dim3(32, 8)>>>(ct, out);
}

// round 4
// speedup vs baseline: 2.3746x; 2.3746x over previous
#include <cuda_runtime.h>
#include <math_constants.h>
#include <cstdint>

typedef long long ll;

// Problem constants
constexpr int Lc   = 2;
constexpr int Bc   = 4;
constexpr int Tc   = 2048;
constexpr int Fc   = 1024;
constexpr int Cc   = 200;
constexpr int Hc   = 8;
constexpr int DFFc = 128;
constexpr int Sc   = Tc + Cc;   // 2248
constexpr int BSc  = Bc * Sc;   // 8992
constexpr int DHc  = Fc / Hc;   // 128
constexpr int SP   = 2304;      // padded S (72*32) for PV K-dim

// ---------------------------------------------------------------------------
// Scratch (device globals; no allocations allowed)
// ---------------------------------------------------------------------------
__device__ float d_src [(size_t)BSc * Fc];
__device__ float d_qb  [(size_t)BSc * Fc];
__device__ float d_kb  [(size_t)BSc * Fc];
__device__ float d_vb  [(size_t)BSc * Fc];
__device__ float d_att [(size_t)BSc * Fc];
__device__ float d_tmp [(size_t)BSc * Fc];
__device__ float d_ffh [(size_t)BSc * DFFc];
__device__ float d_probs[(size_t)Bc * Hc * Sc * SP];       // ~663 MB
__device__ float d_vt  [(size_t)Bc * Fc * SP];             // V transposed, padded
__device__ float d_wt  [Fc * Fc];                          // transposed small weight
__device__ float d_wfq [Fc * Fc];
__device__ float d_wfk [Fc * Fc];
__device__ float d_bfq [Fc];
__device__ float d_bfk [Fc];
__device__ float d_icol[(size_t)Bc * Tc * 3 * Fc];
__device__ float d_ct  [(size_t)Bc * Tc * Fc];

// ---------------------------------------------------------------------------
// PTX helpers (sm_80-compatible only — harness compiles for plain sm_100)
// ---------------------------------------------------------------------------
__device__ __forceinline__ uint32_t smem_u32(const void* p) {
    uint32_t a;
    asm("{ .reg .u64 t; cvta.to.shared.u64 t, %1; cvt.u32.u64 %0, t; }" : "=r"(a) : "l"(p));
    return a;
}

__device__ __forceinline__ void cp_async16(uint32_t dst, const float* src, int pred_bytes) {
    asm volatile("cp.async.cg.shared.global [%0], [%1], 16, %2;"
                 :: "r"(dst), "l"(src), "r"(pred_bytes) : "memory");
}
#define CP_COMMIT() asm volatile("cp.async.commit_group;" ::: "memory")
#define CP_WAIT2()  asm volatile("cp.async.wait_group 2;" ::: "memory")

__device__ __forceinline__ uint32_t cvt_tf32(float f) {
    uint32_t u;
    asm("cvt.rna.tf32.f32 %0, %1;" : "=r"(u) : "f"(f));
    return u;
}

__device__ __forceinline__ void mma_tf32(float* c, const uint32_t* a,
                                         uint32_t b0, uint32_t b1) {
    asm volatile(
        "mma.sync.aligned.m16n8k8.row.col.f32.tf32.tf32.f32 "
        "{%0,%1,%2,%3}, {%4,%5,%6,%7}, {%8,%9}, {%0,%1,%2,%3};"
        : "+f"(c[0]), "+f"(c[1]), "+f"(c[2]), "+f"(c[3])
        : "r"(a[0]), "r"(a[1]), "r"(a[2]), "r"(a[3]), "r"(b0), "r"(b1));
}

// ---------------------------------------------------------------------------
// Tensor-core tf32 GEMM:  C[m,n] = alpha*sum_k A[m,k]*B[n,k] (+bias[n]) (+relu)
// A: [M,K] row-major, B: [N,K] row-major. K % 32 == 0.
// Block tile 128x128x32, 256 threads (warp grid 4(M) x 2(N), warp tile 32x64),
// mma.sync m16n8k8 tf32, 4-stage cp.async pipeline.
// smem per stage: A[128][36] + B[128][36] floats (pad 36 -> conflict-free frags)
// Batched via blockIdx.z = zb*batchH + zh with 64-bit strides.
// ---------------------------------------------------------------------------
constexpr int NSTG = 4;
constexpr int KPAD = 36;
constexpr int STAGE_FLOATS = 2 * 128 * KPAD;           // 9216 floats = 36864 B
constexpr size_t TMMA_SMEM = (size_t)NSTG * STAGE_FLOATS * 4;   // 147456 B

template<bool HASBIAS, bool DORELU>
__global__ void __launch_bounds__(256, 1)
tmma_kernel(int M, int N, int K,
            const float* __restrict__ A, int lda,
            const float* __restrict__ B, int ldb,
            float* __restrict__ C, int ldc,
            const float* __restrict__ bias, float alpha,
            int batchH,
            ll sAb, ll sAh, ll sBb, ll sBh, ll sCb, ll sCh)
{
    extern __shared__ float sm[];

    const int t = threadIdx.x;
    const int wid = t >> 5, lane = t & 31;
    const int warp_m = wid & 3, warp_n = wid >> 2;

    {
        int z = blockIdx.z;
        int zb = z / batchH, zh = z - zb * batchH;
        A += zb * sAb + zh * sAh;
        B += zb * sBb + zh * sBh;
        C += zb * sCb + zh * sCh;
    }
    const int m0 = blockIdx.y * 128, n0 = blockIdx.x * 128;

    const uint32_t smb = smem_u32(sm);

    // ---- async tile loader: thread t loads 4 float4 of A and 4 of B ----
    const int lrow = t >> 1;          // 0..127
    const int lhalf = (t & 1) * 16;   // float offset within 32-float row
    const int KT = K >> 5;

    auto load_stage = [&](int stage, int kc) {
        const int k0 = kc << 5;
        uint32_t aB = smb + (uint32_t)(stage * STAGE_FLOATS) * 4;
        uint32_t bB = aB + 128 * KPAD * 4;
        const int gm = m0 + lrow, gn = n0 + lrow;
        const float* ap = A + (ll)gm * lda + k0 + lhalf;
        const float* bp = B + (ll)gn * ldb + k0 + lhalf;
        uint32_t ad = aB + (lrow * KPAD + lhalf) * 4;
        uint32_t bd = bB + (lrow * KPAD + lhalf) * 4;
        int pa = (gm < M) ? 16 : 0;
        int pb = (gn < N) ? 16 : 0;
        #pragma unroll
        for (int i = 0; i < 4; i++) {
            cp_async16(ad + i * 16, ap + i * 4, pa);
            cp_async16(bd + i * 16, bp + i * 4, pb);
        }
    };

    float c[2][8][4] = {};
    const int aRowBase = warp_m * 32 + (lane >> 2);
    const int bRowBase = warp_n * 64 + (lane >> 2);
    const int kLane = lane & 3;

    // prologue: stages 0..NSTG-2
    #pragma unroll
    for (int s = 0; s < NSTG - 1; s++) { load_stage(s, s); CP_COMMIT(); }

    for (int kt = 0; kt < KT; kt++) {
        const int s = kt & (NSTG - 1);
        CP_WAIT2();
        __syncthreads();

        const float* As = sm + s * STAGE_FLOATS;
        const float* Bs = As + 128 * KPAD;

        #pragma unroll
        for (int kk = 0; kk < 4; kk++) {
            const int kb = kk * 8 + kLane;
            uint32_t a[2][4];
            #pragma unroll
            for (int mt = 0; mt < 2; mt++) {
                int r = aRowBase + mt * 16;
                a[mt][0] = cvt_tf32(As[r * KPAD + kb]);
                a[mt][1] = cvt_tf32(As[(r + 8) * KPAD + kb]);
                a[mt][2] = cvt_tf32(As[r * KPAD + kb + 4]);
                a[mt][3] = cvt_tf32(As[(r + 8) * KPAD + kb + 4]);
            }
            #pragma unroll
            for (int nt = 0; nt < 8; nt++) {
                int n = bRowBase + nt * 8;
                uint32_t b0 = cvt_tf32(Bs[n * KPAD + kb]);
                uint32_t b1 = cvt_tf32(Bs[n * KPAD + kb + 4]);
                mma_tf32(c[0][nt], a[0], b0, b1);
                mma_tf32(c[1][nt], a[1], b0, b1);
            }
        }
        __syncthreads();

        int nc = kt + NSTG - 1;
        if (nc < KT) load_stage(nc & (NSTG - 1), nc);
        CP_COMMIT();
    }

    // ---- epilogue: registers -> gmem ----
    #pragma unroll
    for (int mt = 0; mt < 2; mt++) {
        const int r0 = m0 + warp_m * 32 + mt * 16 + (lane >> 2);
        const int r1 = r0 + 8;
        #pragma unroll
        for (int nt = 0; nt < 8; nt++) {
            const int cb = n0 + warp_n * 64 + nt * 8;
            if (cb < N) {
                const int col = cb + 2 * (lane & 3);
                float2 v0 = make_float2(c[mt][nt][0] * alpha, c[mt][nt][1] * alpha);
                float2 v1 = make_float2(c[mt][nt][2] * alpha, c[mt][nt][3] * alpha);
                if (HASBIAS) {
                    float bx = bias[col], by = bias[col + 1];
                    v0.x += bx; v0.y += by; v1.x += bx; v1.y += by;
                }
                if (DORELU) {
                    v0.x = fmaxf(v0.x, 0.f); v0.y = fmaxf(v0.y, 0.f);
                    v1.x = fmaxf(v1.x, 0.f); v1.y = fmaxf(v1.y, 0.f);
                }
                if (r0 < M) *(float2*)(C + (ll)r0 * ldc + col) = v0;
                if (r1 < M) *(float2*)(C + (ll)r1 * ldc + col) = v1;
            }
        }
    }
}

// ---------------------------------------------------------------------------
// Block reductions
// ---------------------------------------------------------------------------
__device__ __forceinline__ float blkReduceSum(float v) {
    __shared__ float sh[32];
    int lane = threadIdx.x & 31, w = threadIdx.x >> 5;
    #pragma unroll
    for (int o = 16; o; o >>= 1) v += __shfl_xor_sync(0xffffffffu, v, o);
    if (lane == 0) sh[w] = v;
    __syncthreads();
    int nw = blockDim.x >> 5;
    float r = (lane < nw) ? sh[lane] : 0.f;
    #pragma unroll
    for (int o = 16; o; o >>= 1) r += __shfl_xor_sync(0xffffffffu, r, o);
    __syncthreads();
    return r;
}

__device__ __forceinline__ float blkReduceMax(float v) {
    __shared__ float sh[32];
    int lane = threadIdx.x & 31, w = threadIdx.x >> 5;
    #pragma unroll
    for (int o = 16; o; o >>= 1) v = fmaxf(v, __shfl_xor_sync(0xffffffffu, v, o));
    if (lane == 0) sh[w] = v;
    __syncthreads();
    int nw = blockDim.x >> 5;
    float r = (lane < nw) ? sh[lane] : -CUDART_INF_F;
    #pragma unroll
    for (int o = 16; o; o >>= 1) r = fmaxf(r, __shfl_xor_sync(0xffffffffu, r, o));
    __syncthreads();
    return r;
}

// ---------------------------------------------------------------------------
// Small kernels
// ---------------------------------------------------------------------------
__global__ void copy_x_kernel(const float* __restrict__ x, float* __restrict__ src) {
    int idx = blockIdx.x * 256 + threadIdx.x;
    if (idx >= Bc * Tc * Fc) return;
    int b = idx / (Tc * Fc);
    int r = idx - b * (Tc * Fc);
    src[(size_t)b * Sc * Fc + r] = x[idx];
}

__global__ void fill_proto_kernel(const float* __restrict__ proto, float* __restrict__ src) {
    int idx = blockIdx.x * 256 + threadIdx.x;
    if (idx >= Bc * Cc * Fc) return;
    int b   = idx / (Cc * Fc);
    int rem = idx - b * (Cc * Fc);
    int c   = rem / Fc;
    int f   = rem - c * Fc;
    src[(size_t)b * Sc * Fc + (size_t)(Tc + c) * Fc + f] = proto[(size_t)f * Cc + c];
}

__global__ void fuse_bias_kernel(const float* __restrict__ Wi,
                                 const float* __restrict__ bsmall,
                                 const float* __restrict__ badd,
                                 float* __restrict__ outb) {
    int n = blockIdx.x;
    float s = 0.f;
    for (int t = threadIdx.x; t < Fc; t += 256) s += Wi[(size_t)n * Fc + t] * bsmall[t];
    s = blkReduceSum(s);
    if (threadIdx.x == 0) outb[n] = s + badd[n];
}

// softmax over first Sc cols of a SP-wide row; zeros pad cols [Sc,SP)
__global__ void softmax_kernel(float* __restrict__ p) {
    size_t row = blockIdx.x;
    float* r = p + row * (size_t)SP;
    float vals[9];
    float m = -CUDART_INF_F;
    int cnt = 0;
    for (int i = threadIdx.x; i < Sc; i += 256) {
        float v = r[i];
        vals[cnt++] = v;
        m = fmaxf(m, v);
    }
    m = blkReduceMax(m);
    float s = 0.f;
    for (int j = 0; j < cnt; j++) { vals[j] = __expf(vals[j] - m); s += vals[j]; }
    s = blkReduceSum(s);
    float inv = 1.f / s;
    cnt = 0;
    for (int i = threadIdx.x; i < Sc; i += 256) r[i] = vals[cnt++] * inv;
    for (int i = Sc + threadIdx.x; i < SP; i += 256) r[i] = 0.f;
}

__global__ void ln_add_kernel(float* __restrict__ src, const float* __restrict__ delta,
                              const float* __restrict__ g, const float* __restrict__ b) {
    size_t row = blockIdx.x;
    float* sp = src + row * Fc;
    const float* dp = delta + row * Fc;
    float x[4];
    float s = 0.f;
    #pragma unroll
    for (int j = 0; j < 4; j++) {
        int i = threadIdx.x + j * 256;
        x[j] = sp[i] + dp[i];
        s += x[j];
    }
    float mean = blkReduceSum(s) * (1.f / Fc);
    float s2 = 0.f;
    #pragma unroll
    for (int j = 0; j < 4; j++) { float d = x[j] - mean; s2 += d * d; }
    float var = blkReduceSum(s2) * (1.f / Fc);
    float rstd = rsqrtf(var + 1e-5f);
    #pragma unroll
    for (int j = 0; j < 4; j++) {
        int i = threadIdx.x + j * 256;
        sp[i] = (x[j] - mean) * rstd * g[i] + b[i];
    }
}

__global__ void im2col_kernel(const float* __restrict__ src, float* __restrict__ col) {
    int idx = blockIdx.x * 256 + threadIdx.x;
    if (idx >= Bc * Tc * 3 * Fc) return;
    int c3 = idx % (3 * Fc);
    int bt = idx / (3 * Fc);
    int t = bt % Tc, b = bt / Tc;
    int fi = c3 / 3, kk = c3 - fi * 3;
    int tt = t + kk - 1;
    float v = 0.f;
    if (tt >= 0 && tt < Tc) v = src[(size_t)b * Sc * Fc + (size_t)tt * Fc + fi];
    col[idx] = v;
}

// generic transpose: out[c*ldout + r] = in[r*ldin + c]; Cw % 32 == 0, R tail guarded
__global__ void transpose_kernel(const float* __restrict__ in, float* __restrict__ outp,
                                 int R, int ldin, int ldout, ll sIn, ll sOut) {
    __shared__ float tile[32][33];
    int b = blockIdx.z;
    in += b * sIn; outp += b * sOut;
    int r0 = blockIdx.x * 32, c0 = blockIdx.y * 32;
    int tx = threadIdx.x, ty = threadIdx.y;
    #pragma unroll
    for (int i = 0; i < 4; i++) {
        int r = r0 + ty + i * 8;
        if (r < R) tile[ty + i * 8][tx] = in[(ll)r * ldin + c0 + tx];
    }
    __syncthreads();
    int r = r0 + tx;
    if (r < R) {
        #pragma unroll
        for (int i = 0; i < 4; i++) {
            int c = c0 + ty + i * 8;
            outp[(ll)c * ldout + r] = tile[tx][ty + i * 8];
        }
    }
}

__global__ void transpose_relu_kernel(const float* __restrict__ in, float* __restrict__ outp) {
    __shared__ float tile[32][33];
    int b = blockIdx.z;
    int t0 = blockIdx.x * 32, f0 = blockIdx.y * 32;
    int tx = threadIdx.x, ty = threadIdx.y;
    #pragma unroll
    for (int i = 0; i < 4; i++) {
        int tt = t0 + ty + i * 8;
        tile[ty + i * 8][tx] = in[(size_t)b * Tc * Fc + (size_t)tt * Fc + f0 + tx];
    }
    __syncthreads();
    #pragma unroll
    for (int i = 0; i < 4; i++) {
        int f = f0 + ty + i * 8;
        float v = tile[tx][ty + i * 8];
        outp[(size_t)b * Fc * Tc + (size_t)f * Tc + t0 + tx] = fmaxf(v, 0.f);
    }
}

// ---------------------------------------------------------------------------
// Host dispatch
// ---------------------------------------------------------------------------
static void launch_tmma(bool hasbias, bool dorelu,
                        int M, int N, int K,
                        const float* A, int lda, const float* B, int ldb,
                        float* C, int ldc, const float* bias, float alpha,
                        int nz = 1, int batchH = 1,
                        ll sAb = 0, ll sAh = 0, ll sBb = 0, ll sBh = 0,
                        ll sCb = 0, ll sCh = 0)
{
    dim3 grid((N + 127) / 128, (M + 127) / 128, nz);
    if (!hasbias)
        tmma_kernel<false, false><<<grid, 256, TMMA_SMEM>>>(M, N, K, A, lda, B, ldb, C, ldc,
            bias, alpha, batchH, sAb, sAh, sBb, sBh, sCb, sCh);
    else if (!dorelu)
        tmma_kernel<true, false><<<grid, 256, TMMA_SMEM>>>(M, N, K, A, lda, B, ldb, C, ldc,
            bias, alpha, batchH, sAb, sAh, sBb, sBh, sCb, sCh);
    else
        tmma_kernel<true, true><<<grid, 256, TMMA_SMEM>>>(M, N, K, A, lda, B, ldb, C, ldc,
            bias, alpha, batchH, sAb, sAh, sBb, sBh, sCb, sCh);
}

extern "C" void kernel_launch(void* const* d_in, const int* in_sizes, int n_in,
                              void* d_out, int out_size)
{
    const float* x      = (const float*)d_in[0];
    const float* proto  = (const float*)d_in[1];
    const float* wq     = (const float*)d_in[2];
    const float* bq     = (const float*)d_in[3];
    const float* wk     = (const float*)d_in[4];
    const float* bk     = (const float*)d_in[5];
    const float* in_w   = (const float*)d_in[6];
    const float* in_b   = (const float*)d_in[7];
    const float* out_w  = (const float*)d_in[8];
    const float* out_b  = (const float*)d_in[9];
    const float* l1w    = (const float*)d_in[10];
    const float* l1b    = (const float*)d_in[11];
    const float* l2w    = (const float*)d_in[12];
    const float* l2b    = (const float*)d_in[13];
    const float* ln1g   = (const float*)d_in[14];
    const float* ln1b   = (const float*)d_in[15];
    const float* ln2g   = (const float*)d_in[16];
    const float* ln2b   = (const float*)d_in[17];
    const float* embw   = (const float*)d_in[18];
    const float* embb   = (const float*)d_in[19];
    float* out = (float*)d_out;

    cudaFuncSetAttribute(tmma_kernel<false, false>,
                         cudaFuncAttributeMaxDynamicSharedMemorySize, (int)TMMA_SMEM);
    cudaFuncSetAttribute(tmma_kernel<true, false>,
                         cudaFuncAttributeMaxDynamicSharedMemorySize, (int)TMMA_SMEM);
    cudaFuncSetAttribute(tmma_kernel<true, true>,
                         cudaFuncAttributeMaxDynamicSharedMemorySize, (int)TMMA_SMEM);

    float *src, *q, *k, *v, *att, *tmp, *ffh, *probs, *vt, *wt, *wfq, *wfk, *bfq, *bfk, *icol, *ct;
    cudaGetSymbolAddress((void**)&src,  d_src);
    cudaGetSymbolAddress((void**)&q,    d_qb);
    cudaGetSymbolAddress((void**)&k,    d_kb);
    cudaGetSymbolAddress((void**)&v,    d_vb);
    cudaGetSymbolAddress((void**)&att,  d_att);
    cudaGetSymbolAddress((void**)&tmp,  d_tmp);
    cudaGetSymbolAddress((void**)&ffh,  d_ffh);
    cudaGetSymbolAddress((void**)&probs, d_probs);
    cudaGetSymbolAddress((void**)&vt,   d_vt);
    cudaGetSymbolAddress((void**)&wt,   d_wt);
    cudaGetSymbolAddress((void**)&wfq,  d_wfq);
    cudaGetSymbolAddress((void**)&wfk,  d_wfk);
    cudaGetSymbolAddress((void**)&bfq,  d_bfq);
    cudaGetSymbolAddress((void**)&bfk,  d_bfk);
    cudaGetSymbolAddress((void**)&icol, d_icol);
    cudaGetSymbolAddress((void**)&ct,   d_ct);

    const float scale = 0.08838834764831845f;  // 1/sqrt(128)

    copy_x_kernel<<<(Bc * Tc * Fc + 255) / 256, 256>>>(x, src);
    fill_proto_kernel<<<(Bc * Cc * Fc + 255) / 256, 256>>>(proto, src);

    for (int l = 0; l < Lc; l++) {
        const float* Wi   = in_w + (ll)l * 3 * Fc * Fc;   // [3F, F]
        const float* Wiq  = Wi;
        const float* Wik  = Wi + (ll)Fc * Fc;
        const float* Wiv  = Wi + (ll)2 * Fc * Fc;
        const float* bin  = in_b + (ll)l * 3 * Fc;

        // Wfq = Wiq @ wq[l]  (B operand needs K-major -> transpose wq first)
        transpose_kernel<<<dim3(32, 32, 1), dim3(32, 8)>>>(
            wq + (ll)l * Fc * Fc, wt, Fc, Fc, Fc, 0, 0);
        launch_tmma(false, false, Fc, Fc, Fc, Wiq, Fc, wt, Fc, wfq, Fc, nullptr, 1.f);
        transpose_kernel<<<dim3(32, 32, 1), dim3(32, 8)>>>(
            wk + (ll)l * Fc * Fc, wt, Fc, Fc, Fc, 0, 0);
        launch_tmma(false, false, Fc, Fc, Fc, Wik, Fc, wt, Fc, wfk, Fc, nullptr, 1.f);
        fuse_bias_kernel<<<Fc, 256>>>(Wiq, bq + (ll)l * Fc, bin,      bfq);
        fuse_bias_kernel<<<Fc, 256>>>(Wik, bk + (ll)l * Fc, bin + Fc, bfk);

        // Q, K, V : (BS, F)
        launch_tmma(true, false, BSc, Fc, Fc, src, Fc, wfq, Fc, q, Fc, bfq, 1.f);
        launch_tmma(true, false, BSc, Fc, Fc, src, Fc, wfk, Fc, k, Fc, bfk, 1.f);
        launch_tmma(true, false, BSc, Fc, Fc, src, Fc, Wiv, Fc, v, Fc, bin + 2 * Fc, 1.f);

        // V^T per batch: (Sc,F) -> (F, SP)
        transpose_kernel<<<dim3((Sc + 31) / 32, Fc / 32, Bc), dim3(32, 8)>>>(
            v, vt, Sc, Fc, SP, (ll)Sc * Fc, (ll)Fc * SP);

        // scores = scale * Q_h K_h^T  -> probs [b,h][Sc, SP]
        launch_tmma(false, false, Sc, Sc, DHc,
                    q, Fc, k, Fc, probs, SP, nullptr, scale,
                    Bc * Hc, Hc,
                    (ll)Sc * Fc, DHc, (ll)Sc * Fc, DHc,
                    (ll)Hc * Sc * SP, (ll)Sc * SP);
        softmax_kernel<<<Bc * Hc * Sc, 256>>>(probs);

        // att = P V : A=probs (K=SP, zero-padded), B=vt K-major
        launch_tmma(false, false, Sc, DHc, SP,
                    probs, SP, vt, SP, att, Fc, nullptr, 1.f,
                    Bc * Hc, Hc,
                    (ll)Hc * Sc * SP, (ll)Sc * SP,
                    (ll)Fc * SP, (ll)DHc * SP,
                    (ll)Sc * Fc, (ll)DHc);

        // out-proj + residual LN
        launch_tmma(true, false, BSc, Fc, Fc,
                    att, Fc, out_w + (ll)l * Fc * Fc, Fc, tmp, Fc, out_b + (ll)l * Fc, 1.f);
        ln_add_kernel<<<BSc, 256>>>(src, tmp, ln1g + (ll)l * Fc, ln1b + (ll)l * Fc);

        // FFN + residual LN
        launch_tmma(true, true, BSc, DFFc, Fc,
                    src, Fc, l1w + (ll)l * DFFc * Fc, Fc, ffh, DFFc, l1b + (ll)l * DFFc, 1.f);
        launch_tmma(true, false, BSc, Fc, DFFc,
                    ffh, DFFc, l2w + (ll)l * Fc * DFFc, DFFc, tmp, Fc, l2b + (ll)l * Fc, 1.f);
        ln_add_kernel<<<BSc, 256>>>(src, tmp, ln2g + (ll)l * Fc, ln2b + (ll)l * Fc);
    }

    // Conv1d(F->F, k=3, pad=1) as im2col GEMM
    im2col_kernel<<<(Bc * Tc * 3 * Fc + 255) / 256, 256>>>(src, icol);
    launch_tmma(true, false, Bc * Tc, Fc, 3 * Fc,
                icol, 3 * Fc, embw, 3 * Fc, ct, Fc, embb, 1.f);

    transpose_relu_kernel<<<dim3(Tc / 32, Fc / 32, Bc), dim3(32, 8)>>>(ct, out);
}